// round 1
// baseline (speedup 1.0000x reference)
#include <cuda_runtime.h>
#include <math.h>

// Problem constants (fixed by the reference)
constexpr int S_   = 2048;
constexpr int DIM  = 4096;
constexpr int NH   = 32;
constexpr int NKV  = 8;
constexpr int HD   = 128;
constexpr int TOK  = 4096;          // B * S
constexpr int HALF = HD / 2;        // 64 rope pairs

// Scratch in __device__ globals (no runtime allocation allowed)
__device__ float g_q  [(size_t)TOK * DIM];        // 64 MB  [token][32][128]
__device__ float g_k  [(size_t)TOK * NKV * HD];   // 16 MB  [token][8][128]
__device__ float g_v  [(size_t)TOK * NKV * HD];   // 16 MB
__device__ float g_att[(size_t)TOK * DIM];        // 64 MB  [token][32][128]
__device__ float g_cos[S_ * HALF];
__device__ float g_sin[S_ * HALF];

// ---------------------------------------------------------------------------
// SGEMM: C[M,N] = A[M,K] @ B[K,N], all row-major, M,N %128==0, K %8==0.
// 128x128 block tile, BK=8, 256 threads, 8x8 microtile per thread.
// ---------------------------------------------------------------------------
__global__ __launch_bounds__(256) void sgemm_kernel(
    const float* __restrict__ A, const float* __restrict__ B,
    float* __restrict__ C, int M, int N, int K)
{
    __shared__ float As[8][132];   // padded: conflict-free transposed A tile
    __shared__ float Bs[8][128];

    const int tid = threadIdx.x;
    const int bc = blockIdx.x, br = blockIdx.y;

    const int arow = tid >> 1, acol = (tid & 1) << 2;     // A tile: 128x8
    const int brow = tid >> 5, bcol = (tid & 31) << 2;    // B tile: 8x128
    const float* Ap = A + (size_t)(br * 128 + arow) * K + acol;
    const float* Bp = B + (size_t)brow * N + bc * 128 + bcol;

    const int ty = tid >> 4, tx = tid & 15;

    float acc[8][8];
#pragma unroll
    for (int i = 0; i < 8; i++)
#pragma unroll
        for (int j = 0; j < 8; j++) acc[i][j] = 0.f;

    for (int k0 = 0; k0 < K; k0 += 8) {
        float4 av = *(const float4*)(Ap + k0);
        float4 bv = *(const float4*)(Bp + (size_t)k0 * N);
        As[acol + 0][arow] = av.x;
        As[acol + 1][arow] = av.y;
        As[acol + 2][arow] = av.z;
        As[acol + 3][arow] = av.w;
        *(float4*)&Bs[brow][bcol] = bv;
        __syncthreads();

#pragma unroll
        for (int kk = 0; kk < 8; kk++) {
            float4 a0 = *(const float4*)&As[kk][ty * 8];
            float4 a1 = *(const float4*)&As[kk][ty * 8 + 4];
            float4 b0 = *(const float4*)&Bs[kk][tx * 8];
            float4 b1 = *(const float4*)&Bs[kk][tx * 8 + 4];
            float a[8]  = {a0.x, a0.y, a0.z, a0.w, a1.x, a1.y, a1.z, a1.w};
            float bb[8] = {b0.x, b0.y, b0.z, b0.w, b1.x, b1.y, b1.z, b1.w};
#pragma unroll
            for (int i = 0; i < 8; i++)
#pragma unroll
                for (int j = 0; j < 8; j++)
                    acc[i][j] = fmaf(a[i], bb[j], acc[i][j]);
        }
        __syncthreads();
    }

#pragma unroll
    for (int i = 0; i < 8; i++) {
        float* Cp = C + (size_t)(br * 128 + ty * 8 + i) * N + bc * 128 + tx * 8;
        *(float4*)Cp       = make_float4(acc[i][0], acc[i][1], acc[i][2], acc[i][3]);
        *(float4*)(Cp + 4) = make_float4(acc[i][4], acc[i][5], acc[i][6], acc[i][7]);
    }
}

// ---------------------------------------------------------------------------
// RoPE cos/sin table: angle = (pos + start_pos) * 10000^(-(2i)/128), double math.
// ---------------------------------------------------------------------------
__global__ void rope_table_kernel(const int* __restrict__ start_pos)
{
    int idx = blockIdx.x * blockDim.x + threadIdx.x;
    if (idx >= S_ * HALF) return;
    int pos = idx >> 6, i = idx & 63;
    double theta = exp(-((double)(2 * i) / 128.0) * 9.210340371976184); // ln(1e4)
    double ang = (double)(pos + start_pos[0]) * theta;
    g_cos[idx] = (float)cos(ang);
    g_sin[idx] = (float)sin(ang);
}

// In-place RoPE on [TOK][n_heads][128]; one thread per (token, head, pair).
__global__ void rope_apply_kernel(float* __restrict__ buf, int n_heads)
{
    int idx = blockIdx.x * blockDim.x + threadIdx.x;
    int total = TOK * n_heads * HALF;
    if (idx >= total) return;
    int i = idx & 63;
    int rest = idx >> 6;
    int h = rest % n_heads;
    int token = rest / n_heads;
    int pos = token & (S_ - 1);          // S power of two
    float c = g_cos[pos * HALF + i];
    float s = g_sin[pos * HALF + i];
    float* p = buf + ((size_t)token * n_heads + h) * HD + 2 * i;
    float v0 = p[0], v1 = p[1];
    p[0] = v0 * c - v1 * s;
    p[1] = v0 * s + v1 * c;
}

// ---------------------------------------------------------------------------
// Flash-attention (fp32, causal, GQA). Block = (q_tile of 64, head, batch).
// 256 threads: thread (qr = tid/4, c = tid%4) owns query row qr, dim quarter c.
// smem rows padded to 132 floats; key iteration rotated by c to kill 4-way
// bank conflicts on the shared-across-qr K/V rows.
// ---------------------------------------------------------------------------
constexpr int ATTN_SMEM = (64 * 132 * 2 + 64 * 65 + 3 * 64) * (int)sizeof(float); // 84992 B

__global__ __launch_bounds__(256) void attn_kernel()
{
    extern __shared__ float sm[];
    float* Qs   = sm;                 // 64 x 132
    float* KVs  = Qs + 64 * 132;      // 64 x 132 (K, then reused for V)
    float* Ssm  = KVs + 64 * 132;     // 64 x 65
    float* mrow = Ssm + 64 * 65;      // 64
    float* lrow = mrow + 64;          // 64
    float* alph = lrow + 64;          // 64

    const int tid = threadIdx.x;
    const int qt = blockIdx.x, h = blockIdx.y, b = blockIdx.z;
    const int g = h >> 2;             // kv head
    const int qr = tid >> 2, c = tid & 3;
    const float scale = 0.08838834764831845f;   // 1/sqrt(128)

    // Load + pre-scale Q tile
    for (int u = tid * 4; u < 64 * 128; u += 1024) {
        int r = u >> 7, d = u & 127;
        int tq = b * S_ + qt * 64 + r;
        float4 v = *(const float4*)(g_q + ((size_t)tq * NH + h) * HD + d);
        v.x *= scale; v.y *= scale; v.z *= scale; v.w *= scale;
        *(float4*)&Qs[r * 132 + d] = v;
    }
    if (tid < 64) { mrow[tid] = -3.0e38f; lrow[tid] = 0.f; }
    float o[32];
#pragma unroll
    for (int j = 0; j < 32; j++) o[j] = 0.f;
    __syncthreads();

    for (int kt = 0; kt <= qt; kt++) {
        // Load K tile
        for (int u = tid * 4; u < 64 * 128; u += 1024) {
            int r = u >> 7, d = u & 127;
            int tk = b * S_ + kt * 64 + r;
            *(float4*)&KVs[r * 132 + d] =
                *(const float4*)(g_k + ((size_t)tk * NKV + g) * HD + d);
        }
        __syncthreads();

        // Scores: thread handles keys k = 4*kk + c (bank-conflict-free vs c)
        float sacc[16];
#pragma unroll
        for (int kk = 0; kk < 16; kk++) sacc[kk] = 0.f;
        for (int d0 = 0; d0 < 128; d0 += 4) {
            float4 q4 = *(const float4*)&Qs[qr * 132 + d0];
#pragma unroll
            for (int kk = 0; kk < 16; kk++) {
                int k = (kk << 2) + c;
                float4 k4 = *(const float4*)&KVs[k * 132 + d0];
                sacc[kk] += q4.x * k4.x + q4.y * k4.y + q4.z * k4.z + q4.w * k4.w;
            }
        }
#pragma unroll
        for (int kk = 0; kk < 16; kk++) {
            int k = (kk << 2) + c;
            float s = sacc[kk];
            if (kt == qt && k > qr) s -= 1.0e9f;   // reference's additive mask
            Ssm[qr * 65 + k] = s;
        }
        __syncthreads();

        // Load V tile (overwrites K) while 64 threads do online-softmax stats
        for (int u = tid * 4; u < 64 * 128; u += 1024) {
            int r = u >> 7, d = u & 127;
            int tk = b * S_ + kt * 64 + r;
            *(float4*)&KVs[r * 132 + d] =
                *(const float4*)(g_v + ((size_t)tk * NKV + g) * HD + d);
        }
        if (tid < 64) {
            float mprev = mrow[tid];
            float mx = mprev;
            float* srow = &Ssm[tid * 65];
#pragma unroll
            for (int k = 0; k < 64; k++) mx = fmaxf(mx, srow[k]);
            float al = expf(mprev - mx);
            float sum = 0.f;
#pragma unroll
            for (int k = 0; k < 64; k++) {
                float p = expf(srow[k] - mx);
                srow[k] = p;
                sum += p;
            }
            lrow[tid] = lrow[tid] * al + sum;
            mrow[tid] = mx;
            alph[tid] = al;
        }
        __syncthreads();

        // O += P @ V for this thread's 32-dim quarter; key order rotated by c
        float al = alph[qr];
#pragma unroll
        for (int j = 0; j < 32; j++) o[j] *= al;
        for (int k0 = 0; k0 < 64; k0++) {
            int k = (k0 + c) & 63;
            float p = Ssm[qr * 65 + k];
            const float4* vr = (const float4*)&KVs[k * 132 + c * 32];
#pragma unroll
            for (int j4 = 0; j4 < 8; j4++) {
                float4 v4 = vr[j4];
                o[j4 * 4 + 0] += p * v4.x;
                o[j4 * 4 + 1] += p * v4.y;
                o[j4 * 4 + 2] += p * v4.z;
                o[j4 * 4 + 3] += p * v4.w;
            }
        }
        __syncthreads();
    }

    const float inv = 1.0f / lrow[qr];
    const int tq = b * S_ + qt * 64 + qr;
    float* op = g_att + ((size_t)tq * NH + h) * HD + c * 32;
#pragma unroll
    for (int j4 = 0; j4 < 8; j4++) {
        *(float4*)(op + j4 * 4) = make_float4(
            o[j4 * 4 + 0] * inv, o[j4 * 4 + 1] * inv,
            o[j4 * 4 + 2] * inv, o[j4 * 4 + 3] * inv);
    }
}

// ---------------------------------------------------------------------------
// Launch: inputs (metadata order): x, wq, wk, wv, wo, mask, start_pos
// ---------------------------------------------------------------------------
extern "C" void kernel_launch(void* const* d_in, const int* in_sizes, int n_in,
                              void* d_out, int out_size)
{
    const float* x  = (const float*)d_in[0];
    const float* wq = (const float*)d_in[1];
    const float* wk = (const float*)d_in[2];
    const float* wv = (const float*)d_in[3];
    const float* wo = (const float*)d_in[4];
    // d_in[5] (mask) is exactly triu(-1e9) — applied analytically in-kernel.
    const int* start_pos = (const int*)d_in[6];
    float* out = (float*)d_out;

    float *pq, *pk, *pv, *patt;
    cudaGetSymbolAddress((void**)&pq,   g_q);
    cudaGetSymbolAddress((void**)&pk,   g_k);
    cudaGetSymbolAddress((void**)&pv,   g_v);
    cudaGetSymbolAddress((void**)&patt, g_att);

    cudaFuncSetAttribute(attn_kernel,
                         cudaFuncAttributeMaxDynamicSharedMemorySize, ATTN_SMEM);

    // RoPE tables (cheap; depends only on start_pos)
    rope_table_kernel<<<(S_ * HALF + 255) / 256, 256>>>(start_pos);

    // QKV projections
    sgemm_kernel<<<dim3(DIM / 128,        TOK / 128), 256>>>(x, wq, pq, TOK, DIM,      DIM);
    sgemm_kernel<<<dim3((NKV * HD) / 128, TOK / 128), 256>>>(x, wk, pk, TOK, NKV * HD, DIM);
    sgemm_kernel<<<dim3((NKV * HD) / 128, TOK / 128), 256>>>(x, wv, pv, TOK, NKV * HD, DIM);

    // RoPE on Q and K
    rope_apply_kernel<<<(TOK * NH  * HALF) / 256, 256>>>(pq, NH);
    rope_apply_kernel<<<(TOK * NKV * HALF) / 256, 256>>>(pk, NKV);

    // Causal GQA attention
    attn_kernel<<<dim3(S_ / 64, NH, 2), 256, ATTN_SMEM>>>();

    // Output projection straight into d_out
    sgemm_kernel<<<dim3(DIM / 128, TOK / 128), 256>>>(patt, wo, out, TOK, DIM, DIM);
}

// round 3
// speedup vs baseline: 1.8727x; 1.8727x over previous
#include <cuda_runtime.h>
#include <cuda_bf16.h>
#include <math.h>
#include <cstdint>

// Problem constants (fixed by the reference)
constexpr int S_   = 2048;
constexpr int DIM  = 4096;
constexpr int NH   = 32;
constexpr int NKV  = 8;
constexpr int HD   = 128;
constexpr int TOK  = 4096;          // B * S
constexpr int HALF = HD / 2;        // 64 rope pairs
constexpr int KVD  = NKV * HD;      // 1024

// ---------------- scratch (__device__ globals; no runtime alloc) ----------
__device__ float g_q  [(size_t)TOK * DIM];
__device__ float g_k  [(size_t)TOK * KVD];
__device__ float g_v  [(size_t)TOK * KVD];
__device__ float g_att[(size_t)TOK * DIM];
__device__ float g_cos[S_ * HALF];
__device__ float g_sin[S_ * HALF];

// bf16 split operands (hi + lo)
__device__ __nv_bfloat16 g_xh [(size_t)TOK * DIM],  g_xl [(size_t)TOK * DIM];
__device__ __nv_bfloat16 g_ah [(size_t)TOK * DIM],  g_al [(size_t)TOK * DIM];
__device__ __nv_bfloat16 g_wqh[(size_t)DIM * DIM],  g_wql[(size_t)DIM * DIM];   // [N,K]
__device__ __nv_bfloat16 g_wkh[(size_t)KVD * DIM],  g_wkl[(size_t)KVD * DIM];
__device__ __nv_bfloat16 g_wvh[(size_t)KVD * DIM],  g_wvl[(size_t)KVD * DIM];
__device__ __nv_bfloat16 g_woh[(size_t)DIM * DIM],  g_wol[(size_t)DIM * DIM];

// ---------------- helpers ---------------------------------------------
__device__ __forceinline__ uint32_t smem_u32(const void* p) {
    uint32_t a;
    asm("{ .reg .u64 t; cvta.to.shared.u64 t, %1; cvt.u32.u64 %0, t; }"
        : "=r"(a) : "l"(p));
    return a;
}

__device__ __forceinline__ uint32_t sw128(uint32_t o) { return o ^ ((o >> 3) & 0x70); }

__device__ __forceinline__ void cp16(uint32_t dst, const void* src) {
    asm volatile("cp.async.cg.shared.global [%0], [%1], 16;" :: "r"(dst), "l"(src));
}
__device__ __forceinline__ void cp_commit() {
    asm volatile("cp.async.commit_group;");
}
template <int N> __device__ __forceinline__ void cp_wait() {
    asm volatile("cp.async.wait_group %0;" :: "n"(N));
}

__device__ __forceinline__ void ldmx4(uint32_t* r, uint32_t addr) {
    asm volatile("ldmatrix.sync.aligned.m8n8.x4.shared.b16 {%0,%1,%2,%3}, [%4];"
        : "=r"(r[0]), "=r"(r[1]), "=r"(r[2]), "=r"(r[3]) : "r"(addr));
}

__device__ __forceinline__ void mma16816(float* d, const uint32_t* a, const uint32_t* b) {
    asm volatile(
        "mma.sync.aligned.m16n8k16.row.col.f32.bf16.bf16.f32 "
        "{%0,%1,%2,%3}, {%4,%5,%6,%7}, {%8,%9}, {%0,%1,%2,%3};"
        : "+f"(d[0]), "+f"(d[1]), "+f"(d[2]), "+f"(d[3])
        : "r"(a[0]), "r"(a[1]), "r"(a[2]), "r"(a[3]), "r"(b[0]), "r"(b[1]));
}

// ---------------------------------------------------------------------------
// HMMA bf16-split GEMM: C[M,N] = (Ah+Al)[M,K] @ (Bh+Bl)^T, B stored [N,K].
// CTA 128x128, BK=64, 256 threads (8 warps: 4 m-warps x 2 n-warps).
// smem: 2 stages x (Ah,Al,Bh,Bl) x 16KB, SW128-swizzled 128B rows.
// ---------------------------------------------------------------------------
constexpr int GEMM_SMEM = 2 * 4 * 16384 + 1024;   // 132 KB incl. align slack

__global__ __launch_bounds__(256, 1) void gemm_hmma_kernel(
    const __nv_bfloat16* __restrict__ Ah, const __nv_bfloat16* __restrict__ Al,
    const __nv_bfloat16* __restrict__ Bh, const __nv_bfloat16* __restrict__ Bl,
    float* __restrict__ C, int M, int N, int K)
{
    extern __shared__ char smraw[];
    const uint32_t sb = (smem_u32(smraw) + 1023) & ~1023u;

    const int tid  = threadIdx.x;
    const int wid  = tid >> 5, lane = tid & 31;
    const int wm   = wid >> 1, wn = wid & 1;          // 4 x 2 warp grid
    const int row0 = blockIdx.y * 128, col0 = blockIdx.x * 128;

    float d[2][8][4];
#pragma unroll
    for (int i = 0; i < 2; i++)
#pragma unroll
        for (int j = 0; j < 8; j++)
#pragma unroll
            for (int v = 0; v < 4; v++) d[i][j][v] = 0.f;

    const __nv_bfloat16* tens[4] = {Ah, Al, Bh, Bl};
    const int tbase[4] = {row0, row0, col0, col0};
    const int NS = K >> 6;

    // stage loader: 64 bf16 per row (128 B), 128 rows per tensor
    auto load_stage = [&](int s) {
        const uint32_t sbase = sb + (uint32_t)(s & 1) * 65536u;
        const int k0 = s << 6;
#pragma unroll
        for (int t = 0; t < 4; t++) {
            const __nv_bfloat16* gp = tens[t];
            const int rb = tbase[t];
#pragma unroll
            for (int it = 0; it < 4; it++) {
                int u = tid + it * 256;
                int r = u >> 3, kc = u & 7;
                uint32_t dst = sbase + t * 16384 + sw128((uint32_t)(r * 128 + kc * 16));
                cp16(dst, gp + (size_t)(rb + r) * K + k0 + kc * 8);
            }
        }
        cp_commit();
    };

    load_stage(0);

    for (int s = 0; s < NS; s++) {
        if (s + 1 < NS) { load_stage(s + 1); cp_wait<1>(); }
        else            { cp_wait<0>(); }
        __syncthreads();

        const uint32_t abase = sb + (uint32_t)(s & 1) * 65536u;
#pragma unroll
        for (int kk = 0; kk < 4; kk++) {
            uint32_t a_h[2][4], a_l[2][4];
#pragma unroll
            for (int i = 0; i < 2; i++) {
                int r  = 32 * wm + 16 * i + (lane & 15);
                int ch = kk * 2 + (lane >> 4);
                uint32_t ad = abase + sw128((uint32_t)(r * 128 + ch * 16));
                ldmx4(a_h[i], ad);
                ldmx4(a_l[i], ad + 16384);
            }
            uint32_t b_h[8][2], b_l[8][2];
#pragma unroll
            for (int j = 0; j < 4; j++) {
                int quad = lane >> 3, li = lane & 7;
                int r  = 64 * wn + 16 * j + ((quad >> 1) << 3) + li;
                int ch = kk * 2 + (quad & 1);
                uint32_t bd = abase + 32768 + sw128((uint32_t)(r * 128 + ch * 16));
                uint32_t t[4];
                ldmx4(t, bd);
                b_h[2*j][0] = t[0]; b_h[2*j][1] = t[1];
                b_h[2*j+1][0] = t[2]; b_h[2*j+1][1] = t[3];
                ldmx4(t, bd + 16384);
                b_l[2*j][0] = t[0]; b_l[2*j][1] = t[1];
                b_l[2*j+1][0] = t[2]; b_l[2*j+1][1] = t[3];
            }
#pragma unroll
            for (int i = 0; i < 2; i++)
#pragma unroll
                for (int j = 0; j < 8; j++) {
                    mma16816(d[i][j], a_h[i], b_h[j]);
                    mma16816(d[i][j], a_h[i], b_l[j]);
                    mma16816(d[i][j], a_l[i], b_h[j]);
                }
        }
        __syncthreads();
    }

    // epilogue
    const int gid = lane >> 2, tig = lane & 3;
#pragma unroll
    for (int i = 0; i < 2; i++)
#pragma unroll
        for (int j = 0; j < 8; j++) {
            int r = row0 + 32 * wm + 16 * i + gid;
            int c = col0 + 64 * wn + 8 * j + 2 * tig;
            *(float2*)(C + (size_t)r * N + c)       = make_float2(d[i][j][0], d[i][j][1]);
            *(float2*)(C + (size_t)(r + 8) * N + c) = make_float2(d[i][j][2], d[i][j][3]);
        }
}

// ---------------------------------------------------------------------------
// fp32 -> bf16 hi/lo split (elementwise, n % 4 == 0)
// ---------------------------------------------------------------------------
__global__ void split_kernel(const float* __restrict__ src,
                             __nv_bfloat16* __restrict__ hi,
                             __nv_bfloat16* __restrict__ lo, int n)
{
    int i = (blockIdx.x * blockDim.x + threadIdx.x) * 4;
    if (i >= n) return;
    float4 v = *(const float4*)(src + i);
    __nv_bfloat16 h0 = __float2bfloat16(v.x), h1 = __float2bfloat16(v.y);
    __nv_bfloat16 h2 = __float2bfloat16(v.z), h3 = __float2bfloat16(v.w);
    __nv_bfloat16 l0 = __float2bfloat16(v.x - __bfloat162float(h0));
    __nv_bfloat16 l1 = __float2bfloat16(v.y - __bfloat162float(h1));
    __nv_bfloat16 l2 = __float2bfloat16(v.z - __bfloat162float(h2));
    __nv_bfloat16 l3 = __float2bfloat16(v.w - __bfloat162float(h3));
    *(__nv_bfloat162*)(hi + i)     = __nv_bfloat162(h0, h1);
    *(__nv_bfloat162*)(hi + i + 2) = __nv_bfloat162(h2, h3);
    *(__nv_bfloat162*)(lo + i)     = __nv_bfloat162(l0, l1);
    *(__nv_bfloat162*)(lo + i + 2) = __nv_bfloat162(l2, l3);
}

// fp32 [K,N] -> transposed bf16 hi/lo [N,K] (smem-tiled; K,N % 32 == 0)
__global__ void splitT_kernel(const float* __restrict__ src,
                              __nv_bfloat16* __restrict__ hi,
                              __nv_bfloat16* __restrict__ lo, int K, int N)
{
    __shared__ float t[32][33];
    const int k0 = blockIdx.y * 32, n0 = blockIdx.x * 32;
    const int tx = threadIdx.x, ty = threadIdx.y;      // (32, 8)
#pragma unroll
    for (int i = 0; i < 4; i++)
        t[ty + 8 * i][tx] = src[(size_t)(k0 + ty + 8 * i) * N + n0 + tx];
    __syncthreads();
#pragma unroll
    for (int i = 0; i < 4; i++) {
        float v = t[tx][ty + 8 * i];
        int n = n0 + ty + 8 * i, k = k0 + tx;
        __nv_bfloat16 h = __float2bfloat16(v);
        __nv_bfloat16 l = __float2bfloat16(v - __bfloat162float(h));
        hi[(size_t)n * K + k] = h;
        lo[(size_t)n * K + k] = l;
    }
}

// ---------------------------------------------------------------------------
// RoPE table + apply
// ---------------------------------------------------------------------------
__global__ void rope_table_kernel(const int* __restrict__ start_pos)
{
    int idx = blockIdx.x * blockDim.x + threadIdx.x;
    if (idx >= S_ * HALF) return;
    int pos = idx >> 6, i = idx & 63;
    double theta = exp(-((double)(2 * i) / 128.0) * 9.210340371976184);
    double ang = (double)(pos + start_pos[0]) * theta;
    g_cos[idx] = (float)cos(ang);
    g_sin[idx] = (float)sin(ang);
}

__global__ void rope_apply_kernel(float* __restrict__ buf, int n_heads)
{
    int idx = blockIdx.x * blockDim.x + threadIdx.x;
    int total = TOK * n_heads * HALF;
    if (idx >= total) return;
    int i = idx & 63;
    int rest = idx >> 6;
    int h = rest % n_heads;
    int token = rest / n_heads;
    int pos = token & (S_ - 1);
    float c = g_cos[pos * HALF + i];
    float s = g_sin[pos * HALF + i];
    float* p = buf + ((size_t)token * n_heads + h) * HD + 2 * i;
    float v0 = p[0], v1 = p[1];
    p[0] = v0 * c - v1 * s;
    p[1] = v0 * s + v1 * c;
}

// ---------------------------------------------------------------------------
// Flash-attention (fp32, causal, GQA) — unchanged
// ---------------------------------------------------------------------------
constexpr int ATTN_SMEM = (64 * 132 * 2 + 64 * 65 + 3 * 64) * (int)sizeof(float);

__global__ __launch_bounds__(256) void attn_kernel()
{
    extern __shared__ float sm[];
    float* Qs   = sm;
    float* KVs  = Qs + 64 * 132;
    float* Ssm  = KVs + 64 * 132;
    float* mrow = Ssm + 64 * 65;
    float* lrow = mrow + 64;
    float* alph = lrow + 64;

    const int tid = threadIdx.x;
    const int qt = blockIdx.x, h = blockIdx.y, b = blockIdx.z;
    const int g = h >> 2;
    const int qr = tid >> 2, c = tid & 3;
    const float scale = 0.08838834764831845f;

    for (int u = tid * 4; u < 64 * 128; u += 1024) {
        int r = u >> 7, d = u & 127;
        int tq = b * S_ + qt * 64 + r;
        float4 v = *(const float4*)(g_q + ((size_t)tq * NH + h) * HD + d);
        v.x *= scale; v.y *= scale; v.z *= scale; v.w *= scale;
        *(float4*)&Qs[r * 132 + d] = v;
    }
    if (tid < 64) { mrow[tid] = -3.0e38f; lrow[tid] = 0.f; }
    float o[32];
#pragma unroll
    for (int j = 0; j < 32; j++) o[j] = 0.f;
    __syncthreads();

    for (int kt = 0; kt <= qt; kt++) {
        for (int u = tid * 4; u < 64 * 128; u += 1024) {
            int r = u >> 7, d = u & 127;
            int tk = b * S_ + kt * 64 + r;
            *(float4*)&KVs[r * 132 + d] =
                *(const float4*)(g_k + ((size_t)tk * NKV + g) * HD + d);
        }
        __syncthreads();

        float sacc[16];
#pragma unroll
        for (int kk = 0; kk < 16; kk++) sacc[kk] = 0.f;
        for (int d0 = 0; d0 < 128; d0 += 4) {
            float4 q4 = *(const float4*)&Qs[qr * 132 + d0];
#pragma unroll
            for (int kk = 0; kk < 16; kk++) {
                int k = (kk << 2) + c;
                float4 k4 = *(const float4*)&KVs[k * 132 + d0];
                sacc[kk] += q4.x * k4.x + q4.y * k4.y + q4.z * k4.z + q4.w * k4.w;
            }
        }
#pragma unroll
        for (int kk = 0; kk < 16; kk++) {
            int k = (kk << 2) + c;
            float s = sacc[kk];
            if (kt == qt && k > qr) s -= 1.0e9f;
            Ssm[qr * 65 + k] = s;
        }
        __syncthreads();

        for (int u = tid * 4; u < 64 * 128; u += 1024) {
            int r = u >> 7, d = u & 127;
            int tk = b * S_ + kt * 64 + r;
            *(float4*)&KVs[r * 132 + d] =
                *(const float4*)(g_v + ((size_t)tk * NKV + g) * HD + d);
        }
        if (tid < 64) {
            float mprev = mrow[tid];
            float mx = mprev;
            float* srow = &Ssm[tid * 65];
#pragma unroll
            for (int k = 0; k < 64; k++) mx = fmaxf(mx, srow[k]);
            float al = expf(mprev - mx);
            float sum = 0.f;
#pragma unroll
            for (int k = 0; k < 64; k++) {
                float p = expf(srow[k] - mx);
                srow[k] = p;
                sum += p;
            }
            lrow[tid] = lrow[tid] * al + sum;
            mrow[tid] = mx;
            alph[tid] = al;
        }
        __syncthreads();

        float al = alph[qr];
#pragma unroll
        for (int j = 0; j < 32; j++) o[j] *= al;
        for (int k0 = 0; k0 < 64; k0++) {
            int k = (k0 + c) & 63;
            float p = Ssm[qr * 65 + k];
            const float4* vr = (const float4*)&KVs[k * 132 + c * 32];
#pragma unroll
            for (int j4 = 0; j4 < 8; j4++) {
                float4 v4 = vr[j4];
                o[j4 * 4 + 0] += p * v4.x;
                o[j4 * 4 + 1] += p * v4.y;
                o[j4 * 4 + 2] += p * v4.z;
                o[j4 * 4 + 3] += p * v4.w;
            }
        }
        __syncthreads();
    }

    const float inv = 1.0f / lrow[qr];
    const int tq = b * S_ + qt * 64 + qr;
    float* op = g_att + ((size_t)tq * NH + h) * HD + c * 32;
#pragma unroll
    for (int j4 = 0; j4 < 8; j4++) {
        *(float4*)(op + j4 * 4) = make_float4(
            o[j4 * 4 + 0] * inv, o[j4 * 4 + 1] * inv,
            o[j4 * 4 + 2] * inv, o[j4 * 4 + 3] * inv);
    }
}

// ---------------------------------------------------------------------------
// Launch: inputs (metadata order): x, wq, wk, wv, wo, mask, start_pos
// ---------------------------------------------------------------------------
extern "C" void kernel_launch(void* const* d_in, const int* in_sizes, int n_in,
                              void* d_out, int out_size)
{
    const float* x  = (const float*)d_in[0];
    const float* wq = (const float*)d_in[1];
    const float* wk = (const float*)d_in[2];
    const float* wv = (const float*)d_in[3];
    const float* wo = (const float*)d_in[4];
    const int* start_pos = (const int*)d_in[6];
    float* out = (float*)d_out;

    float *pq, *pk, *pv, *patt;
    __nv_bfloat16 *xh, *xl, *ah, *al, *wqh, *wql, *wkh, *wkl, *wvh, *wvl, *woh, *wol;
    cudaGetSymbolAddress((void**)&pq,   g_q);
    cudaGetSymbolAddress((void**)&pk,   g_k);
    cudaGetSymbolAddress((void**)&pv,   g_v);
    cudaGetSymbolAddress((void**)&patt, g_att);
    cudaGetSymbolAddress((void**)&xh,  g_xh);  cudaGetSymbolAddress((void**)&xl,  g_xl);
    cudaGetSymbolAddress((void**)&ah,  g_ah);  cudaGetSymbolAddress((void**)&al,  g_al);
    cudaGetSymbolAddress((void**)&wqh, g_wqh); cudaGetSymbolAddress((void**)&wql, g_wql);
    cudaGetSymbolAddress((void**)&wkh, g_wkh); cudaGetSymbolAddress((void**)&wkl, g_wkl);
    cudaGetSymbolAddress((void**)&wvh, g_wvh); cudaGetSymbolAddress((void**)&wvl, g_wvl);
    cudaGetSymbolAddress((void**)&woh, g_woh); cudaGetSymbolAddress((void**)&wol, g_wol);

    cudaFuncSetAttribute(attn_kernel,
                         cudaFuncAttributeMaxDynamicSharedMemorySize, ATTN_SMEM);
    cudaFuncSetAttribute(gemm_hmma_kernel,
                         cudaFuncAttributeMaxDynamicSharedMemorySize, GEMM_SMEM);

    // RoPE tables
    rope_table_kernel<<<(S_ * HALF + 255) / 256, 256>>>(start_pos);

    // split-convert activations and (transposed) weights to bf16 hi/lo
    int nx = TOK * DIM;
    split_kernel<<<nx / 1024, 256>>>(x, xh, xl, nx);
    dim3 tb(32, 8);
    splitT_kernel<<<dim3(DIM / 32, DIM / 32), tb>>>(wq, wqh, wql, DIM, DIM);
    splitT_kernel<<<dim3(KVD / 32, DIM / 32), tb>>>(wk, wkh, wkl, DIM, KVD);
    splitT_kernel<<<dim3(KVD / 32, DIM / 32), tb>>>(wv, wvh, wvl, DIM, KVD);
    splitT_kernel<<<dim3(DIM / 32, DIM / 32), tb>>>(wo, woh, wol, DIM, DIM);

    // QKV projections on tensor cores (HMMA)
    gemm_hmma_kernel<<<dim3(DIM / 128, TOK / 128), 256, GEMM_SMEM>>>(
        xh, xl, wqh, wql, pq, TOK, DIM, DIM);
    gemm_hmma_kernel<<<dim3(KVD / 128, TOK / 128), 256, GEMM_SMEM>>>(
        xh, xl, wkh, wkl, pk, TOK, KVD, DIM);
    gemm_hmma_kernel<<<dim3(KVD / 128, TOK / 128), 256, GEMM_SMEM>>>(
        xh, xl, wvh, wvl, pv, TOK, KVD, DIM);

    // RoPE on Q and K
    rope_apply_kernel<<<(TOK * NH  * HALF) / 256, 256>>>(pq, NH);
    rope_apply_kernel<<<(TOK * NKV * HALF) / 256, 256>>>(pk, NKV);

    // Causal GQA attention (fp32)
    attn_kernel<<<dim3(S_ / 64, NH, 2), 256, ATTN_SMEM>>>();

    // Output projection on tensor cores
    split_kernel<<<nx / 1024, 256>>>(patt, ah, al, nx);
    gemm_hmma_kernel<<<dim3(DIM / 128, TOK / 128), 256, GEMM_SMEM>>>(
        ah, al, woh, wol, out, TOK, DIM, DIM);
}

// round 5
// speedup vs baseline: 4.4387x; 2.3702x over previous
#include <cuda_runtime.h>
#include <cuda_bf16.h>
#include <math.h>
#include <cstdint>

// Problem constants (fixed by the reference)
constexpr int S_   = 2048;
constexpr int DIM  = 4096;
constexpr int NH   = 32;
constexpr int NKV  = 8;
constexpr int HD   = 128;
constexpr int TOK  = 4096;          // B * S
constexpr int HALF = HD / 2;        // 64 rope pairs
constexpr int KVD  = NKV * HD;      // 1024

// ---------------- scratch (__device__ globals; no runtime alloc) ----------
__device__ float g_q  [(size_t)TOK * DIM];
__device__ float g_k  [(size_t)TOK * KVD];
__device__ float g_v  [(size_t)TOK * KVD];
__device__ float g_cos[S_ * HALF];
__device__ float g_sin[S_ * HALF];

// bf16 split operands (hi + lo)
__device__ __nv_bfloat16 g_xh [(size_t)TOK * DIM],  g_xl [(size_t)TOK * DIM]; // x, then reused as Q(hi/lo)
__device__ __nv_bfloat16 g_ah [(size_t)TOK * DIM],  g_al [(size_t)TOK * DIM]; // attention out
__device__ __nv_bfloat16 g_kh [(size_t)TOK * KVD],  g_kl [(size_t)TOK * KVD];
__device__ __nv_bfloat16 g_vth[(size_t)TOK * KVD],  g_vtl[(size_t)TOK * KVD]; // V^T [b][g][d][key]
__device__ __nv_bfloat16 g_wqh[(size_t)DIM * DIM],  g_wql[(size_t)DIM * DIM]; // [N,K]
__device__ __nv_bfloat16 g_wkh[(size_t)KVD * DIM],  g_wkl[(size_t)KVD * DIM];
__device__ __nv_bfloat16 g_wvh[(size_t)KVD * DIM],  g_wvl[(size_t)KVD * DIM];
__device__ __nv_bfloat16 g_woh[(size_t)DIM * DIM],  g_wol[(size_t)DIM * DIM];

// ---------------- helpers ---------------------------------------------
__device__ __forceinline__ uint32_t smem_u32(const void* p) {
    uint32_t a;
    asm("{ .reg .u64 t; cvta.to.shared.u64 t, %1; cvt.u32.u64 %0, t; }"
        : "=r"(a) : "l"(p));
    return a;
}

__device__ __forceinline__ uint32_t sw128(uint32_t o) { return o ^ ((o >> 3) & 0x70); }

__device__ __forceinline__ void cp16(uint32_t dst, const void* src) {
    asm volatile("cp.async.cg.shared.global [%0], [%1], 16;" :: "r"(dst), "l"(src));
}
__device__ __forceinline__ void cp_commit() {
    asm volatile("cp.async.commit_group;");
}
template <int N> __device__ __forceinline__ void cp_wait() {
    asm volatile("cp.async.wait_group %0;" :: "n"(N));
}

__device__ __forceinline__ void ldmx4(uint32_t* r, uint32_t addr) {
    asm volatile("ldmatrix.sync.aligned.m8n8.x4.shared.b16 {%0,%1,%2,%3}, [%4];"
        : "=r"(r[0]), "=r"(r[1]), "=r"(r[2]), "=r"(r[3]) : "r"(addr));
}

__device__ __forceinline__ void mma16816(float* d, const uint32_t* a, const uint32_t* b) {
    asm volatile(
        "mma.sync.aligned.m16n8k16.row.col.f32.bf16.bf16.f32 "
        "{%0,%1,%2,%3}, {%4,%5,%6,%7}, {%8,%9}, {%0,%1,%2,%3};"
        : "+f"(d[0]), "+f"(d[1]), "+f"(d[2]), "+f"(d[3])
        : "r"(a[0]), "r"(a[1]), "r"(a[2]), "r"(a[3]), "r"(b[0]), "r"(b[1]));
}

__device__ __forceinline__ uint32_t pack2(__nv_bfloat16 a, __nv_bfloat16 b) {
    __nv_bfloat162 t(a, b);                 // a = low half
    return *(uint32_t*)&t;
}
__device__ __forceinline__ void split2(float a, float b, uint32_t& h, uint32_t& l) {
    __nv_bfloat16 ha = __float2bfloat16(a), hb = __float2bfloat16(b);
    h = pack2(ha, hb);
    l = pack2(__float2bfloat16(a - __bfloat162float(ha)),
              __float2bfloat16(b - __bfloat162float(hb)));
}

// ---------------------------------------------------------------------------
// HMMA bf16-split GEMM (validated round 3)
// ---------------------------------------------------------------------------
constexpr int GEMM_SMEM = 2 * 4 * 16384 + 1024;

__global__ __launch_bounds__(256, 1) void gemm_hmma_kernel(
    const __nv_bfloat16* __restrict__ Ah, const __nv_bfloat16* __restrict__ Al,
    const __nv_bfloat16* __restrict__ Bh, const __nv_bfloat16* __restrict__ Bl,
    float* __restrict__ C, int M, int N, int K)
{
    extern __shared__ char smraw[];
    const uint32_t sb = (smem_u32(smraw) + 1023) & ~1023u;

    const int tid  = threadIdx.x;
    const int wid  = tid >> 5, lane = tid & 31;
    const int wm   = wid >> 1, wn = wid & 1;
    const int row0 = blockIdx.y * 128, col0 = blockIdx.x * 128;

    float d[2][8][4];
#pragma unroll
    for (int i = 0; i < 2; i++)
#pragma unroll
        for (int j = 0; j < 8; j++)
#pragma unroll
            for (int v = 0; v < 4; v++) d[i][j][v] = 0.f;

    const __nv_bfloat16* tens[4] = {Ah, Al, Bh, Bl};
    const int tbase[4] = {row0, row0, col0, col0};
    const int NS = K >> 6;

    auto load_stage = [&](int s) {
        const uint32_t sbase = sb + (uint32_t)(s & 1) * 65536u;
        const int k0 = s << 6;
#pragma unroll
        for (int t = 0; t < 4; t++) {
            const __nv_bfloat16* gp = tens[t];
            const int rb = tbase[t];
#pragma unroll
            for (int it = 0; it < 4; it++) {
                int u = tid + it * 256;
                int r = u >> 3, kc = u & 7;
                uint32_t dst = sbase + t * 16384 + sw128((uint32_t)(r * 128 + kc * 16));
                cp16(dst, gp + (size_t)(rb + r) * K + k0 + kc * 8);
            }
        }
        cp_commit();
    };

    load_stage(0);

    for (int s = 0; s < NS; s++) {
        if (s + 1 < NS) { load_stage(s + 1); cp_wait<1>(); }
        else            { cp_wait<0>(); }
        __syncthreads();

        const uint32_t abase = sb + (uint32_t)(s & 1) * 65536u;
#pragma unroll
        for (int kk = 0; kk < 4; kk++) {
            uint32_t a_h[2][4], a_l[2][4];
#pragma unroll
            for (int i = 0; i < 2; i++) {
                int r  = 32 * wm + 16 * i + (lane & 15);
                int ch = kk * 2 + (lane >> 4);
                uint32_t ad = abase + sw128((uint32_t)(r * 128 + ch * 16));
                ldmx4(a_h[i], ad);
                ldmx4(a_l[i], ad + 16384);
            }
            uint32_t b_h[8][2], b_l[8][2];
#pragma unroll
            for (int j = 0; j < 4; j++) {
                int quad = lane >> 3, li = lane & 7;
                int r  = 64 * wn + 16 * j + ((quad >> 1) << 3) + li;
                int ch = kk * 2 + (quad & 1);
                uint32_t bd = abase + 32768 + sw128((uint32_t)(r * 128 + ch * 16));
                uint32_t t[4];
                ldmx4(t, bd);
                b_h[2*j][0] = t[0]; b_h[2*j][1] = t[1];
                b_h[2*j+1][0] = t[2]; b_h[2*j+1][1] = t[3];
                ldmx4(t, bd + 16384);
                b_l[2*j][0] = t[0]; b_l[2*j][1] = t[1];
                b_l[2*j+1][0] = t[2]; b_l[2*j+1][1] = t[3];
            }
#pragma unroll
            for (int i = 0; i < 2; i++)
#pragma unroll
                for (int j = 0; j < 8; j++) {
                    mma16816(d[i][j], a_h[i], b_h[j]);
                    mma16816(d[i][j], a_h[i], b_l[j]);
                    mma16816(d[i][j], a_l[i], b_h[j]);
                }
        }
        __syncthreads();
    }

    const int gid = lane >> 2, tig = lane & 3;
#pragma unroll
    for (int i = 0; i < 2; i++)
#pragma unroll
        for (int j = 0; j < 8; j++) {
            int r = row0 + 32 * wm + 16 * i + gid;
            int c = col0 + 64 * wn + 8 * j + 2 * tig;
            *(float2*)(C + (size_t)r * N + c)       = make_float2(d[i][j][0], d[i][j][1]);
            *(float2*)(C + (size_t)(r + 8) * N + c) = make_float2(d[i][j][2], d[i][j][3]);
        }
}

// ---------------------------------------------------------------------------
// conversion kernels
// ---------------------------------------------------------------------------
__global__ void split_kernel(const float* __restrict__ src,
                             __nv_bfloat16* __restrict__ hi,
                             __nv_bfloat16* __restrict__ lo, int n)
{
    int i = (blockIdx.x * blockDim.x + threadIdx.x) * 4;
    if (i >= n) return;
    float4 v = *(const float4*)(src + i);
    uint32_t h0, l0, h1, l1;
    split2(v.x, v.y, h0, l0);
    split2(v.z, v.w, h1, l1);
    *(uint32_t*)(hi + i)     = h0; *(uint32_t*)(hi + i + 2) = h1;
    *(uint32_t*)(lo + i)     = l0; *(uint32_t*)(lo + i + 2) = l1;
}

__global__ void splitT_kernel(const float* __restrict__ src,
                              __nv_bfloat16* __restrict__ hi,
                              __nv_bfloat16* __restrict__ lo, int K, int N)
{
    __shared__ float t[32][33];
    const int k0 = blockIdx.y * 32, n0 = blockIdx.x * 32;
    const int tx = threadIdx.x, ty = threadIdx.y;
#pragma unroll
    for (int i = 0; i < 4; i++)
        t[ty + 8 * i][tx] = src[(size_t)(k0 + ty + 8 * i) * N + n0 + tx];
    __syncthreads();
#pragma unroll
    for (int i = 0; i < 4; i++) {
        float v = t[tx][ty + 8 * i];
        int n = n0 + ty + 8 * i, k = k0 + tx;
        __nv_bfloat16 h = __float2bfloat16(v);
        __nv_bfloat16 l = __float2bfloat16(v - __bfloat162float(h));
        hi[(size_t)n * K + k] = h;
        lo[(size_t)n * K + k] = l;
    }
}

__global__ void rope_table_kernel(const int* __restrict__ start_pos)
{
    int idx = blockIdx.x * blockDim.x + threadIdx.x;
    if (idx >= S_ * HALF) return;
    int pos = idx >> 6, i = idx & 63;
    double theta = exp(-((double)(2 * i) / 128.0) * 9.210340371976184);
    double ang = (double)(pos + start_pos[0]) * theta;
    g_cos[idx] = (float)cos(ang);
    g_sin[idx] = (float)sin(ang);
}

// fused RoPE + scale + bf16 hi/lo split (src fp32 [token][n_heads*128])
__global__ void rope_split_kernel(const float* __restrict__ src,
                                  __nv_bfloat16* __restrict__ hi,
                                  __nv_bfloat16* __restrict__ lo,
                                  int n_heads, float scale)
{
    int idx = blockIdx.x * blockDim.x + threadIdx.x;
    int total = TOK * n_heads * HALF;
    if (idx >= total) return;
    int i = idx & 63;
    int rest = idx >> 6;
    int h = rest % n_heads;
    int token = rest / n_heads;
    int pos = token & (S_ - 1);
    float c = g_cos[pos * HALF + i];
    float s = g_sin[pos * HALF + i];
    size_t base = ((size_t)token * n_heads + h) * HD + 2 * i;
    float v0 = src[base], v1 = src[base + 1];
    float r0 = (v0 * c - v1 * s) * scale;
    float r1 = (v0 * s + v1 * c) * scale;
    uint32_t hp, lp;
    split2(r0, r1, hp, lp);
    *(uint32_t*)(hi + base) = hp;
    *(uint32_t*)(lo + base) = lp;
}

// V fp32 [token][g*128+d] -> bf16 hi/lo transposed [b][g][d][key]
__global__ void vtrans_kernel(const float* __restrict__ src,
                              __nv_bfloat16* __restrict__ hi,
                              __nv_bfloat16* __restrict__ lo)
{
    __shared__ float t[32][33];
    const int bg = blockIdx.z;               // b*NKV + g
    const int b = bg / NKV, g = bg % NKV;
    const int k0 = blockIdx.x * 32, d0 = blockIdx.y * 32;
    const int tx = threadIdx.x, ty = threadIdx.y;  // (32, 8)
#pragma unroll
    for (int i = 0; i < 4; i++)
        t[ty + 8 * i][tx] =
            src[(size_t)(b * S_ + k0 + ty + 8 * i) * KVD + g * HD + d0 + tx];
    __syncthreads();
#pragma unroll
    for (int i = 0; i < 4; i++) {
        float v = t[tx][ty + 8 * i];          // V[key=k0+tx][d=d0+ty+8i]
        int d = d0 + ty + 8 * i, key = k0 + tx;
        __nv_bfloat16 h = __float2bfloat16(v);
        __nv_bfloat16 l = __float2bfloat16(v - __bfloat162float(h));
        size_t dst = ((size_t)bg * HD + d) * S_ + key;
        hi[dst] = h;
        lo[dst] = l;
    }
}

// ---------------------------------------------------------------------------
// HMMA flash-attention, bf16 split, causal, GQA.
// CTA = (128-query tile, head, batch); 8 warps x 16 rows; K-tile = 64 keys.
// smem: Q(hi/lo) 64KB resident + 2 x 64KB KV stages.
// ---------------------------------------------------------------------------
constexpr int ATTN_SMEM = 65536 + 2 * 65536 + 1024;   // 197632

__global__ __launch_bounds__(256, 1) void attn_hmma_kernel(
    const __nv_bfloat16* __restrict__ qh, const __nv_bfloat16* __restrict__ ql,
    const __nv_bfloat16* __restrict__ kh, const __nv_bfloat16* __restrict__ kl,
    const __nv_bfloat16* __restrict__ vth, const __nv_bfloat16* __restrict__ vtl,
    __nv_bfloat16* __restrict__ oh, __nv_bfloat16* __restrict__ ol)
{
    extern __shared__ char smraw[];
    const uint32_t sb = (smem_u32(smraw) + 1023) & ~1023u;

    const int tid  = threadIdx.x;
    const int w    = tid >> 5, lane = tid & 31;
    const int quad = lane >> 3, li = lane & 7;
    const int qt = blockIdx.x, h = blockIdx.y, b = blockIdx.z;
    const int g = h >> 2;
    const int bg = b * NKV + g;

    // ---- Q tile (plain loads into swizzled smem; hi at sb, lo at +32768) ----
    {
        const __nv_bfloat16* qp[2] = {qh, ql};
#pragma unroll
        for (int it = 0; it < 16; it++) {
            int u = tid + it * 256;
            int p = u >> 11, uu = u & 2047;
            int r = uu >> 4, ch = uu & 15;
            uint4 val = *(const uint4*)(qp[p] +
                (size_t)(b * S_ + qt * 128 + r) * DIM + h * HD + ch * 8);
            *(uint4*)(smraw + (sb - smem_u32(smraw)) + p * 32768 +
                      (ch >> 3) * 16384 + sw128((uint32_t)(r * 128 + (ch & 7) * 16))) = val;
        }
    }

    // ---- KV stage loader (cp.async) ----
    auto load_kv = [&](int kt, int buf) {
        const uint32_t st = sb + 65536 + (uint32_t)buf * 65536u;
        const __nv_bfloat16* kp[2] = {kh, kl};
#pragma unroll
        for (int p = 0; p < 2; p++)
#pragma unroll
            for (int it = 0; it < 4; it++) {
                int u = tid + it * 256;
                int r = u >> 4, ch = u & 15;
                uint32_t dst = st + p * 16384 + (ch >> 3) * 8192 +
                               sw128((uint32_t)(r * 128 + (ch & 7) * 16));
                cp16(dst, kp[p] + (size_t)(b * S_ + kt * 64 + r) * KVD + g * HD + ch * 8);
            }
        const __nv_bfloat16* vp[2] = {vth, vtl};
#pragma unroll
        for (int p = 0; p < 2; p++)
#pragma unroll
            for (int it = 0; it < 4; it++) {
                int u = tid + it * 256;
                int r = u >> 3, ch = u & 7;
                uint32_t dst = st + 32768 + p * 16384 +
                               sw128((uint32_t)(r * 128 + ch * 16));
                cp16(dst, vp[p] + ((size_t)bg * HD + r) * S_ + kt * 64 + ch * 8);
            }
        cp_commit();
    };

    const int nkt = 2 * qt + 2;
    load_kv(0, 0);

    // ---- per-thread softmax / output state ----
    float m0 = -1e30f, m1 = -1e30f, l0 = 0.f, l1 = 0.f;
    float of[16][4];
#pragma unroll
    for (int j = 0; j < 16; j++)
#pragma unroll
        for (int v = 0; v < 4; v++) of[j][v] = 0.f;

    const int row_lo = qt * 128 + 16 * w + (lane >> 2);
    const int row_hi = row_lo + 8;

    for (int kt = 0; kt < nkt; kt++) {
        const int buf = kt & 1;
        if (kt + 1 < nkt) { load_kv(kt + 1, buf ^ 1); cp_wait<1>(); }
        else              { cp_wait<0>(); }
        __syncthreads();

        const uint32_t st  = sb + 65536 + (uint32_t)buf * 65536u;
        const uint32_t stv = st + 32768;

        // ---- S = Q K^T (3-term split) ----
        float sfr[8][4];
#pragma unroll
        for (int j = 0; j < 8; j++)
#pragma unroll
            for (int v = 0; v < 4; v++) sfr[j][v] = 0.f;

#pragma unroll
        for (int ks = 0; ks < 8; ks++) {
            uint32_t qhf[4], qlf[4], tt[4];
            {
                int ch = 2 * ks + (lane >> 4);
                int r  = 16 * w + (lane & 15);
                uint32_t qa = sb + (ch >> 3) * 16384 +
                              sw128((uint32_t)(r * 128 + (ch & 7) * 16));
                ldmx4(qhf, qa);
                ldmx4(qlf, qa + 32768);
            }
            uint32_t kb_h[8][2], kb_l[8][2];
            int chb = 2 * ks + (quad & 1);
#pragma unroll
            for (int jj = 0; jj < 4; jj++) {
                int rb = 16 * jj + ((quad >> 1) << 3) + li;
                uint32_t ka = st + (chb >> 3) * 8192 +
                              sw128((uint32_t)(rb * 128 + (chb & 7) * 16));
                ldmx4(tt, ka);
                kb_h[2*jj][0] = tt[0]; kb_h[2*jj][1] = tt[1];
                kb_h[2*jj+1][0] = tt[2]; kb_h[2*jj+1][1] = tt[3];
                ldmx4(tt, ka + 16384);
                kb_l[2*jj][0] = tt[0]; kb_l[2*jj][1] = tt[1];
                kb_l[2*jj+1][0] = tt[2]; kb_l[2*jj+1][1] = tt[3];
            }
#pragma unroll
            for (int j = 0; j < 8; j++) {
                mma16816(sfr[j], qhf, kb_h[j]);
                mma16816(sfr[j], qhf, kb_l[j]);
                mma16816(sfr[j], qlf, kb_h[j]);
            }
        }

        // ---- causal mask (only the last two K-tiles can cross the diagonal) --
        if (kt >= 2 * qt) {
            int colb = kt * 64 + 2 * (lane & 3);
#pragma unroll
            for (int j = 0; j < 8; j++) {
                int c0 = colb + 8 * j, c1 = c0 + 1;
                if (c0 > row_lo) sfr[j][0] = -1e30f;
                if (c1 > row_lo) sfr[j][1] = -1e30f;
                if (c0 > row_hi) sfr[j][2] = -1e30f;
                if (c1 > row_hi) sfr[j][3] = -1e30f;
            }
        }

        // ---- online softmax ----
        float mx0 = m0, mx1 = m1;
#pragma unroll
        for (int j = 0; j < 8; j++) {
            mx0 = fmaxf(mx0, fmaxf(sfr[j][0], sfr[j][1]));
            mx1 = fmaxf(mx1, fmaxf(sfr[j][2], sfr[j][3]));
        }
        mx0 = fmaxf(mx0, __shfl_xor_sync(0xffffffffu, mx0, 1));
        mx0 = fmaxf(mx0, __shfl_xor_sync(0xffffffffu, mx0, 2));
        mx1 = fmaxf(mx1, __shfl_xor_sync(0xffffffffu, mx1, 1));
        mx1 = fmaxf(mx1, __shfl_xor_sync(0xffffffffu, mx1, 2));

        float a0 = __expf(m0 - mx0), a1 = __expf(m1 - mx1);
        m0 = mx0; m1 = mx1;

        float rs0 = 0.f, rs1 = 0.f;
#pragma unroll
        for (int j = 0; j < 8; j++) {
            sfr[j][0] = __expf(sfr[j][0] - mx0);
            sfr[j][1] = __expf(sfr[j][1] - mx0);
            sfr[j][2] = __expf(sfr[j][2] - mx1);
            sfr[j][3] = __expf(sfr[j][3] - mx1);
            rs0 += sfr[j][0] + sfr[j][1];
            rs1 += sfr[j][2] + sfr[j][3];
        }
        l0 = l0 * a0 + rs0;
        l1 = l1 * a1 + rs1;
#pragma unroll
        for (int j = 0; j < 16; j++) {
            of[j][0] *= a0; of[j][1] *= a0;
            of[j][2] *= a1; of[j][3] *= a1;
        }

        // ---- O += P V (3-term split) ----
#pragma unroll
        for (int kk = 0; kk < 4; kk++) {
            uint32_t pah[4], pal[4];
            split2(sfr[2*kk][0],   sfr[2*kk][1],   pah[0], pal[0]);
            split2(sfr[2*kk][2],   sfr[2*kk][3],   pah[1], pal[1]);
            split2(sfr[2*kk+1][0], sfr[2*kk+1][1], pah[2], pal[2]);
            split2(sfr[2*kk+1][2], sfr[2*kk+1][3], pah[3], pal[3]);

            int chv = 2 * kk + (quad & 1);
#pragma unroll
            for (int jj = 0; jj < 8; jj++) {
                int rb = 16 * jj + ((quad >> 1) << 3) + li;
                uint32_t va = stv + sw128((uint32_t)(rb * 128 + chv * 16));
                uint32_t th[4], tl[4];
                ldmx4(th, va);
                ldmx4(tl, va + 16384);
                uint32_t bh0[2] = {th[0], th[1]}, bh1[2] = {th[2], th[3]};
                uint32_t bl0[2] = {tl[0], tl[1]}, bl1[2] = {tl[2], tl[3]};
                mma16816(of[2*jj],   pah, bh0);
                mma16816(of[2*jj],   pah, bl0);
                mma16816(of[2*jj],   pal, bh0);
                mma16816(of[2*jj+1], pah, bh1);
                mma16816(of[2*jj+1], pah, bl1);
                mma16816(of[2*jj+1], pal, bh1);
            }
        }
        __syncthreads();
    }

    // ---- finalize: lane-reduce l, normalize, write split bf16 output ----
    l0 += __shfl_xor_sync(0xffffffffu, l0, 1);
    l0 += __shfl_xor_sync(0xffffffffu, l0, 2);
    l1 += __shfl_xor_sync(0xffffffffu, l1, 1);
    l1 += __shfl_xor_sync(0xffffffffu, l1, 2);
    const float inv0 = 1.f / l0, inv1 = 1.f / l1;

    const size_t r0 = (size_t)(b * S_ + qt * 128 + 16 * w + (lane >> 2)) * DIM;
    const size_t r1 = r0 + 8 * DIM;
#pragma unroll
    for (int j = 0; j < 16; j++) {
        int col = h * HD + 8 * j + 2 * (lane & 3);
        uint32_t hp, lp;
        split2(of[j][0] * inv0, of[j][1] * inv0, hp, lp);
        *(uint32_t*)(oh + r0 + col) = hp;
        *(uint32_t*)(ol + r0 + col) = lp;
        split2(of[j][2] * inv1, of[j][3] * inv1, hp, lp);
        *(uint32_t*)(oh + r1 + col) = hp;
        *(uint32_t*)(ol + r1 + col) = lp;
    }
}

// ---------------------------------------------------------------------------
// Launch: inputs (metadata order): x, wq, wk, wv, wo, mask, start_pos
// ---------------------------------------------------------------------------
extern "C" void kernel_launch(void* const* d_in, const int* in_sizes, int n_in,
                              void* d_out, int out_size)
{
    const float* x  = (const float*)d_in[0];
    const float* wq = (const float*)d_in[1];
    const float* wk = (const float*)d_in[2];
    const float* wv = (const float*)d_in[3];
    const float* wo = (const float*)d_in[4];
    const int* start_pos = (const int*)d_in[6];
    float* out = (float*)d_out;

    float *pq, *pk, *pv;
    __nv_bfloat16 *xh, *xl, *ah, *al, *kh, *kl, *vth, *vtl;
    __nv_bfloat16 *wqh, *wql, *wkh, *wkl, *wvh, *wvl, *woh, *wol;
    cudaGetSymbolAddress((void**)&pq,  g_q);
    cudaGetSymbolAddress((void**)&pk,  g_k);
    cudaGetSymbolAddress((void**)&pv,  g_v);
    cudaGetSymbolAddress((void**)&xh,  g_xh);  cudaGetSymbolAddress((void**)&xl,  g_xl);
    cudaGetSymbolAddress((void**)&ah,  g_ah);  cudaGetSymbolAddress((void**)&al,  g_al);
    cudaGetSymbolAddress((void**)&kh,  g_kh);  cudaGetSymbolAddress((void**)&kl,  g_kl);
    cudaGetSymbolAddress((void**)&vth, g_vth); cudaGetSymbolAddress((void**)&vtl, g_vtl);
    cudaGetSymbolAddress((void**)&wqh, g_wqh); cudaGetSymbolAddress((void**)&wql, g_wql);
    cudaGetSymbolAddress((void**)&wkh, g_wkh); cudaGetSymbolAddress((void**)&wkl, g_wkl);
    cudaGetSymbolAddress((void**)&wvh, g_wvh); cudaGetSymbolAddress((void**)&wvl, g_wvl);
    cudaGetSymbolAddress((void**)&woh, g_woh); cudaGetSymbolAddress((void**)&wol, g_wol);

    cudaFuncSetAttribute(gemm_hmma_kernel,
                         cudaFuncAttributeMaxDynamicSharedMemorySize, GEMM_SMEM);
    cudaFuncSetAttribute(attn_hmma_kernel,
                         cudaFuncAttributeMaxDynamicSharedMemorySize, ATTN_SMEM);

    // RoPE tables
    rope_table_kernel<<<(S_ * HALF + 255) / 256, 256>>>(start_pos);

    // split-convert activations and (transposed) weights
    int nx = TOK * DIM;
    split_kernel<<<nx / 1024, 256>>>(x, xh, xl, nx);
    dim3 tb(32, 8);
    splitT_kernel<<<dim3(DIM / 32, DIM / 32), tb>>>(wq, wqh, wql, DIM, DIM);
    splitT_kernel<<<dim3(KVD / 32, DIM / 32), tb>>>(wk, wkh, wkl, DIM, KVD);
    splitT_kernel<<<dim3(KVD / 32, DIM / 32), tb>>>(wv, wvh, wvl, DIM, KVD);
    splitT_kernel<<<dim3(DIM / 32, DIM / 32), tb>>>(wo, woh, wol, DIM, DIM);

    // QKV projections (HMMA)
    gemm_hmma_kernel<<<dim3(DIM / 128, TOK / 128), 256, GEMM_SMEM>>>(
        xh, xl, wqh, wql, pq, TOK, DIM, DIM);
    gemm_hmma_kernel<<<dim3(KVD / 128, TOK / 128), 256, GEMM_SMEM>>>(
        xh, xl, wkh, wkl, pk, TOK, KVD, DIM);
    gemm_hmma_kernel<<<dim3(KVD / 128, TOK / 128), 256, GEMM_SMEM>>>(
        xh, xl, wvh, wvl, pv, TOK, KVD, DIM);

    // RoPE + scale + split Q (reuses xh/xl), RoPE + split K, transpose-split V
    const float qscale = 0.08838834764831845f;   // 1/sqrt(128)
    rope_split_kernel<<<(TOK * NH  * HALF) / 256, 256>>>(pq, xh, xl, NH, qscale);
    rope_split_kernel<<<(TOK * NKV * HALF) / 256, 256>>>(pk, kh, kl, NKV, 1.0f);
    vtrans_kernel<<<dim3(S_ / 32, HD / 32, 2 * NKV), tb>>>(pv, vth, vtl);

    // HMMA causal GQA flash attention -> split bf16 output (ah/al)
    attn_hmma_kernel<<<dim3(S_ / 128, NH, 2), 256, ATTN_SMEM>>>(
        xh, xl, kh, kl, vth, vtl, ah, al);

    // Output projection (HMMA) straight into d_out
    gemm_hmma_kernel<<<dim3(DIM / 128, TOK / 128), 256, GEMM_SMEM>>>(
        ah, al, woh, wol, out, TOK, DIM, DIM);
}